// round 1
// baseline (speedup 1.0000x reference)
#include <cuda_runtime.h>
#include <cuda_bf16.h>
#include <math_constants.h>

// Problem constants
#define DD 128
#define NN 8192
#define KK 256

// Scratch (device globals: allocation-free rule)
__device__ float g_At[KK * DD * DD];    // At[c][d][e], 16 MB
__device__ float g_Amu[KK * DD];        // Amu[c][d]
__device__ float g_sq[NN * KK];         // sq[n][c], 8 MB

// ---------------------------------------------------------------------------
// Kernel 0: transpose N_A (16384 x 256) -> At (256 x 16384)
// N_A[d,e,c] at (d*128+e)*256 + c ; row r = d*128+e
// ---------------------------------------------------------------------------
__global__ void transpose_kernel(const float* __restrict__ NA) {
    __shared__ float t[32][33];
    int r0 = blockIdx.x * 32;
    int c0 = blockIdx.y * 32;
    int tx = threadIdx.x, ty = threadIdx.y;
#pragma unroll
    for (int i = ty; i < 32; i += 8)
        t[i][tx] = NA[(r0 + i) * KK + c0 + tx];
    __syncthreads();
#pragma unroll
    for (int i = ty; i < 32; i += 8)
        g_At[(c0 + i) * (DD * DD) + r0 + tx] = t[tx][i];
}

// ---------------------------------------------------------------------------
// Kernel 1: Amu[c][d] = sum_e At[c][d][e] * mu[e][c]   (mu is (D,K): mu[e*K+c])
// one block per c, 128 threads (d)
// ---------------------------------------------------------------------------
__global__ void amu_kernel(const float* __restrict__ mu) {
    __shared__ float smu[DD];
    int c = blockIdx.x;
    int d = threadIdx.x;
    smu[d] = mu[d * KK + c];
    __syncthreads();
    const float* A = g_At + c * (DD * DD) + d * DD;
    float s = 0.f;
#pragma unroll 8
    for (int e = 0; e < DD; e++) s += A[e] * smu[e];
    g_Amu[c * DD + d] = s;
}

// ---------------------------------------------------------------------------
// Kernel 2: fused GEMM + squared-distance reduction.
// Block (nt, c): Y = A_c @ X[:, n0:n0+128]  (128x128x128),
//                sq[n][c] = sum_d (Y[d][n] - Amu[c][d])^2
// 256 threads, 8x8 register tile, 128 KB dynamic smem.
// ---------------------------------------------------------------------------
__global__ __launch_bounds__(256, 1) void gemm_sq_kernel(const float* __restrict__ X) {
    extern __shared__ float sm[];
    float* As = sm;            // [k][d] 128*128
    float* Xs = sm + DD * DD;  // [k][n] 128*128

    const int c  = blockIdx.y;
    const int n0 = blockIdx.x * 128;
    const int tid = threadIdx.x;
    const int tx = tid & 15;   // n sub-tile
    const int ty = tid >> 4;   // d sub-tile

    // Load A_c, transposing [d][e] -> As[e][d]
    const float* Ac = g_At + c * (DD * DD);
    for (int i = tid * 4; i < DD * DD; i += 1024) {
        float4 v = *(const float4*)(Ac + i);
        int d = i >> 7, e = i & 127;
        As[(e + 0) * DD + d] = v.x;
        As[(e + 1) * DD + d] = v.y;
        As[(e + 2) * DD + d] = v.z;
        As[(e + 3) * DD + d] = v.w;
    }
    // Load X tile: Xs[e][j] = X[e][n0+j]
    for (int i = tid * 4; i < DD * 128; i += 1024) {
        int e = i >> 7, j = i & 127;
        *(float4*)(Xs + i) = *(const float4*)(X + e * NN + n0 + j);
    }
    __syncthreads();

    float acc[8][8] = {};
#pragma unroll 4
    for (int k = 0; k < DD; k++) {
        float a[8], b[8];
        *(float4*)(a)     = *(const float4*)(As + k * DD + ty * 8);
        *(float4*)(a + 4) = *(const float4*)(As + k * DD + ty * 8 + 4);
        *(float4*)(b)     = *(const float4*)(Xs + k * DD + tx * 8);
        *(float4*)(b + 4) = *(const float4*)(Xs + k * DD + tx * 8 + 4);
#pragma unroll
        for (int i = 0; i < 8; i++)
#pragma unroll
            for (int j = 0; j < 8; j++)
                acc[i][j] += a[i] * b[j];
    }

    // Epilogue: partial sums of (Y - Amu)^2 over this thread's 8 d-rows
    float amu[8];
    const float* Am = g_Amu + c * DD + ty * 8;
#pragma unroll
    for (int i = 0; i < 8; i++) amu[i] = Am[i];

    float part[8];
#pragma unroll
    for (int j = 0; j < 8; j++) {
        float s = 0.f;
#pragma unroll
        for (int i = 0; i < 8; i++) {
            float v = acc[i][j] - amu[i];
            s += v * v;
        }
        part[j] = s;
    }

    __syncthreads();           // done reading As/Xs
    float* red = sm;           // [16][128]
#pragma unroll
    for (int j = 0; j < 8; j++) red[ty * 128 + tx * 8 + j] = part[j];
    __syncthreads();

    if (tid < 128) {
        float s = 0.f;
#pragma unroll
        for (int t = 0; t < 16; t++) s += red[t * 128 + tid];
        g_sq[(n0 + tid) * KK + c] = s;
    }
}

// ---------------------------------------------------------------------------
// Kernel 3: softmax over c (K=256) per column n, writing Pi into out rows D..D+K.
// Block handles 32 n-columns; tile [32][257] in smem.
// ---------------------------------------------------------------------------
__global__ __launch_bounds__(256) void softmax_kernel(const float* __restrict__ gamma_p,
                                                      float* __restrict__ out) {
    __shared__ float tile[32 * 257];
    const float g = *gamma_p;
    const int n0 = blockIdx.x * 32;
    const int tid = threadIdx.x;

    for (int i = tid; i < 32 * KK; i += 256) {
        int nl = i >> 8, c = i & 255;
        tile[nl * 257 + c] = g_sq[(n0 + nl) * KK + c];
    }
    __syncthreads();

    const int warp = tid >> 5, lane = tid & 31;
    for (int r = warp; r < 32; r += 8) {
        float v[8];
        float m = -CUDART_INF_F;
#pragma unroll
        for (int u = 0; u < 8; u++) {
            v[u] = g * tile[r * 257 + lane + 32 * u];
            m = fmaxf(m, v[u]);
        }
#pragma unroll
        for (int o = 16; o > 0; o >>= 1)
            m = fmaxf(m, __shfl_xor_sync(0xffffffffu, m, o));
        float s = 0.f;
#pragma unroll
        for (int u = 0; u < 8; u++) {
            v[u] = __expf(v[u] - m);
            s += v[u];
        }
#pragma unroll
        for (int o = 16; o > 0; o >>= 1)
            s += __shfl_xor_sync(0xffffffffu, s, o);
        float inv = __frcp_rn(s);
#pragma unroll
        for (int u = 0; u < 8; u++)
            tile[r * 257 + lane + 32 * u] = v[u] * inv;
    }
    __syncthreads();

    // write Pi: out[(D + c) * N + n0 + j]
    for (int i = tid; i < 32 * KK; i += 256) {
        int c = i >> 5, j = i & 31;
        out[(DD + c) * NN + n0 + j] = tile[j * 257 + c];
    }
}

// ---------------------------------------------------------------------------
extern "C" void kernel_launch(void* const* d_in, const int* in_sizes, int n_in,
                              void* d_out, int out_size) {
    const float* X     = (const float*)d_in[0];  // (D, N)
    const float* NA    = (const float*)d_in[1];  // (D, D, K)
    const float* Nmu   = (const float*)d_in[2];  // (D, K)
    const float* gamma = (const float*)d_in[3];  // scalar
    float* out = (float*)d_out;                  // (D+K, N)

    cudaFuncSetAttribute(gemm_sq_kernel,
                         cudaFuncAttributeMaxDynamicSharedMemorySize,
                         2 * DD * DD * (int)sizeof(float));

    // rows 0..D-1 of out = X verbatim
    cudaMemcpyAsync(out, X, (size_t)DD * NN * sizeof(float),
                    cudaMemcpyDeviceToDevice, 0);

    transpose_kernel<<<dim3((DD * DD) / 32, KK / 32), dim3(32, 8)>>>(NA);
    amu_kernel<<<KK, DD>>>(Nmu);
    gemm_sq_kernel<<<dim3(NN / 128, KK), 256,
                     2 * DD * DD * sizeof(float)>>>(X);
    softmax_kernel<<<NN / 32, 256>>>(gamma, out);
}

// round 6
// speedup vs baseline: 11.0411x; 11.0411x over previous
#include <cuda_runtime.h>
#include <cuda_fp16.h>
#include <cstdint>
#include <math_constants.h>

#define DD 128
#define NN 8192
#define KK 256
#define RQ 8256            // d<=e pair rows
#define RTOT 8384          // + 128 linear rows (131 * 64)
#define KC 64              // k-chunk (halves)
#define NCH (RTOT / KC)    // 131
#define NST 4              // pipeline stages
#define STAGE_BYTES 32768  // 16KB A + 16KB B per stage

// ------------- device scratch (no allocations allowed) ---------------------
__device__ __align__(16) float  g_At[KK * DD * DD];      // A_c row-major per c (16 MB)
__device__ __align__(16) __half g_C[(size_t)KK * RTOT];  // coeff matrix fp16 (4.3 MB)
__device__ __align__(16) __half g_F[(size_t)NN * RTOT];  // feature matrix fp16 (137 MB)
__device__ __align__(16) float  g_sq[(size_t)KK * NN];   // sq, c-major (8 MB)
__device__ float g_kc[KK];                               // per-c constant
__device__ __align__(16) unsigned short g_lut[RTOT];     // r -> (d<<8)|e

// ------------------------------- PTX helpers -------------------------------
__device__ __forceinline__ uint32_t smem_u32(const void* p) {
    uint32_t a;
    asm("{ .reg .u64 t; cvta.to.shared.u64 t, %1; cvt.u32.u64 %0, t; }"
        : "=r"(a) : "l"(p));
    return a;
}
__device__ __forceinline__ void cp16h(uint32_t dst, const __half* src) {
    asm volatile("cp.async.cg.shared.global [%0], [%1], 16;"
                 :: "r"(dst), "l"((unsigned long long)__cvta_generic_to_global(src)));
}
#define CP_COMMIT() asm volatile("cp.async.commit_group;" ::: "memory")
#define CP_WAIT3()  asm volatile("cp.async.wait_group 3;" ::: "memory")

__device__ __forceinline__ void ldsm4(uint32_t* r, uint32_t addr) {
    asm volatile("ldmatrix.sync.aligned.m8n8.x4.shared.b16 {%0,%1,%2,%3}, [%4];"
                 : "=r"(r[0]), "=r"(r[1]), "=r"(r[2]), "=r"(r[3]) : "r"(addr));
}
__device__ __forceinline__ void mma16816(float* c, const uint32_t* a,
                                         uint32_t b0, uint32_t b1) {
    asm volatile(
        "mma.sync.aligned.m16n8k16.row.col.f32.f16.f16.f32 "
        "{%0,%1,%2,%3}, {%4,%5,%6,%7}, {%8,%9}, {%0,%1,%2,%3};"
        : "+f"(c[0]), "+f"(c[1]), "+f"(c[2]), "+f"(c[3])
        : "r"(a[0]), "r"(a[1]), "r"(a[2]), "r"(a[3]), "r"(b0), "r"(b1));
}

// ---------------------------------------------------------------------------
// Kernel 0: transpose N_A (16384 x 256) -> At (256 x 16384)
// ---------------------------------------------------------------------------
__global__ void transpose_kernel(const float* __restrict__ NA) {
    __shared__ float t[32][33];
    int r0 = blockIdx.x * 32;
    int c0 = blockIdx.y * 32;
    int tx = threadIdx.x, ty = threadIdx.y;
#pragma unroll
    for (int i = ty; i < 32; i += 8)
        t[i][tx] = NA[(r0 + i) * KK + c0 + tx];
    __syncthreads();
#pragma unroll
    for (int i = ty; i < 32; i += 8)
        g_At[(size_t)(c0 + i) * (DD * DD) + r0 + tx] = t[tx][i];
}

// ---------------------------------------------------------------------------
// Kernel 1: pair-index lookup table  r -> (d<<8)|e
// ---------------------------------------------------------------------------
__global__ void lut_kernel() {
    int t = threadIdx.x;
    if (t < 128) {
        int d = t;
        int base = d * DD - (d * (d - 1)) / 2;
        for (int e = d; e < DD; e++)
            g_lut[base + e - d] = (unsigned short)((d << 8) | e);
    } else {
        int e = t - 128;
        g_lut[RQ + e] = (unsigned short)((128 << 8) | e);
    }
}

// ---------------------------------------------------------------------------
// Kernel 2: per-c coefficients. G_c = A_c^T A_c, w_c = G mu, k_c = mu^T G mu.
// C row (fp16): pairs get (d==e ? 1 : 2)*G_de, linear rows get -2*w_d.
// ---------------------------------------------------------------------------
__global__ __launch_bounds__(256, 2) void gbuild_kernel(const float* __restrict__ mu) {
    extern __shared__ float sm[];
    float* sA  = sm;                   // [128][132]
    float* smu = sm + 128 * 132;       // [128]
    float* ss  = smu + 128;            // [128]
    const int c = blockIdx.x, tid = threadIdx.x;

    const float* Ac = g_At + (size_t)c * (DD * DD);
    for (int i = tid * 4; i < DD * DD; i += 1024) {
        float4 v = *(const float4*)(Ac + i);
        int k = i >> 7, e = i & 127;
        *(float4*)(sA + k * 132 + e) = v;
    }
    if (tid < DD) smu[tid] = mu[tid * KK + c];
    __syncthreads();

    if (tid < DD) {                    // s[k] = A_c row k . mu
        float s = 0.f;
#pragma unroll 8
        for (int e = 0; e < DD; e++) s += sA[tid * 132 + e] * smu[e];
        ss[tid] = s;
    }
    __syncthreads();
    if (tid < DD) {                    // w[d] = sum_k A[k][d] s[k]
        float w = 0.f;
#pragma unroll 8
        for (int k = 0; k < DD; k++) w += sA[k * 132 + tid] * ss[k];
        g_C[(size_t)c * RTOT + RQ + tid] = __float2half(-2.f * w);
    }
    if (tid == 0) {                    // k_c = ||s||^2
        float kk = 0.f;
        for (int k = 0; k < DD; k++) kk += ss[k] * ss[k];
        g_kc[c] = kk;
    }

    // G = A^T A, 8x8 per thread
    const int tx = tid & 15, ty = tid >> 4;
    float acc[8][8] = {};
#pragma unroll 4
    for (int k = 0; k < DD; k++) {
        float a[8], b[8];
        *(float4*)(a)     = *(const float4*)(sA + k * 132 + ty * 8);
        *(float4*)(a + 4) = *(const float4*)(sA + k * 132 + ty * 8 + 4);
        *(float4*)(b)     = *(const float4*)(sA + k * 132 + tx * 8);
        *(float4*)(b + 4) = *(const float4*)(sA + k * 132 + tx * 8 + 4);
#pragma unroll
        for (int i = 0; i < 8; i++)
#pragma unroll
            for (int j = 0; j < 8; j++)
                acc[i][j] += a[i] * b[j];
    }
    __half* Crow = g_C + (size_t)c * RTOT;
#pragma unroll
    for (int i = 0; i < 8; i++) {
        int d = ty * 8 + i;
        int sd = d * DD - (d * (d - 1)) / 2;
#pragma unroll
        for (int j = 0; j < 8; j++) {
            int e = tx * 8 + j;
            if (e >= d)
                Crow[sd + e - d] = __float2half((e == d ? 1.f : 2.f) * acc[i][j]);
        }
    }
}

// ---------------------------------------------------------------------------
// Kernel 3: feature matrix F[n][r] = x_d[n]*x_e[n] in fp16 (xs[128]==1 linear)
// ---------------------------------------------------------------------------
__global__ __launch_bounds__(256) void fbuild_kernel(const float* __restrict__ X) {
    __shared__ __align__(16) float xs[129 * 33 + 1];
    __shared__ __align__(16) unsigned short slut[RTOT];
    const int tid = threadIdx.x;
    const int n0 = blockIdx.x * 32;

    for (int i = tid; i < DD * 32; i += 256) {
        int e = i >> 5, nl = i & 31;
        xs[e * 33 + nl] = X[e * NN + n0 + nl];
    }
    if (tid < 32) xs[128 * 33 + tid] = 1.0f;
    for (int i = tid; i < RTOT; i += 256) slut[i] = g_lut[i];
    __syncthreads();

    for (int nl = 0; nl < 32; nl++) {
        __half* dst = g_F + (size_t)(n0 + nl) * RTOT;
        for (int r4 = tid * 4; r4 < RTOT; r4 += 1024) {
            uint2 lw = *(const uint2*)(slut + r4);
            int d0 = (lw.x >> 8) & 0xFF,  e0 = lw.x & 0xFF;
            int d1 = (lw.x >> 24) & 0xFF, e1 = (lw.x >> 16) & 0xFF;
            int d2 = (lw.y >> 8) & 0xFF,  e2 = lw.y & 0xFF;
            int d3 = (lw.y >> 24) & 0xFF, e3 = (lw.y >> 16) & 0xFF;
            __half2 h0 = __floats2half2_rn(xs[d0 * 33 + nl] * xs[e0 * 33 + nl],
                                           xs[d1 * 33 + nl] * xs[e1 * 33 + nl]);
            __half2 h1 = __floats2half2_rn(xs[d2 * 33 + nl] * xs[e2 * 33 + nl],
                                           xs[d3 * 33 + nl] * xs[e3 * 33 + nl]);
            uint2 v;
            v.x = *reinterpret_cast<uint32_t*>(&h0);
            v.y = *reinterpret_cast<uint32_t*>(&h1);
            *(uint2*)(dst + r4) = v;
        }
    }
}

// ---------------------------------------------------------------------------
// Kernel 4: fp16 mma.sync GEMM  sq[c,n] = sum_r C[c,r] * F[n,r]
// CTA 128x128, 8 warps (2m x 4n), warp 64x32, k-chunk 64, 4-stage cp.async.
// ---------------------------------------------------------------------------
__global__ __launch_bounds__(256, 1) void mma_kernel() {
    extern __shared__ char dsm[];
    const uint32_t sbase = smem_u32(dsm);
    const int tid = threadIdx.x, lane = tid & 31, wid = tid >> 5;
    const int c0 = blockIdx.x * 128, n0 = blockIdx.y * 128;
    const int mwarp = wid & 1, nwarp = wid >> 1;

    // pipeline loader: 8 x cp16 per thread per stage (A 16KB + B 16KB)
    auto load_stage = [&](int st, int ch) {
        uint32_t ab = sbase + st * STAGE_BYTES;
        uint32_t bb = ab + 16384;
        const __half* As = g_C + (size_t)c0 * RTOT + ch * KC;
        const __half* Bs = g_F + (size_t)n0 * RTOT + ch * KC;
#pragma unroll
        for (int j = 0; j < 4; j++) {
            int seg = tid + j * 256;          // 0..1023
            int row = seg >> 3, s = seg & 7;  // row 0..127, 16B seg 0..7
            uint32_t off = (uint32_t)(row * 128 + ((s ^ (row & 7)) << 4));
            cp16h(ab + off, As + (size_t)row * RTOT + s * 8);
            cp16h(bb + off, Bs + (size_t)row * RTOT + s * 8);
        }
        CP_COMMIT();
    };

    for (int s = 0; s < NST - 1; s++) load_stage(s, s);

    float acc[4][4][4] = {};

    const int laneRow = lane & 7;
    const int grp = lane >> 3;               // 0..3
    const int rowOffA = (grp & 1) << 3;      // A: +8 rows for odd groups
    const int kgA = grp >> 1;                // A: +8 k for groups 2,3
    const int rowOffB = (lane >> 4) << 3;    // B: +8 n-rows for t16..31
    const int kgB = (lane >> 3) & 1;         // B: +8 k for groups 1,3
    const int mA = mwarp * 64, nB = nwarp * 32;

    for (int i = 0; i < NCH; i++) {
        if (i + NST - 1 < NCH) load_stage((i + NST - 1) & 3, i + NST - 1);
        else CP_COMMIT();
        CP_WAIT3();
        __syncthreads();

        uint32_t ab = sbase + (i & 3) * STAGE_BYTES;
        uint32_t bb = ab + 16384;
#pragma unroll
        for (int ks = 0; ks < 4; ks++) {     // 4 x k16 steps within chunk
            uint32_t a[4][4], b[2][4];
#pragma unroll
            for (int m = 0; m < 4; m++) {
                int row = mA + 16 * m + laneRow + rowOffA;
                uint32_t addr = ab + (uint32_t)(row * 128 +
                                (((ks * 2 + kgA) ^ laneRow) << 4));
                ldsm4(a[m], addr);
            }
#pragma unroll
            for (int j = 0; j < 2; j++) {
                int row = nB + 16 * j + laneRow + rowOffB;
                uint32_t addr = bb + (uint32_t)(row * 128 +
                                (((ks * 2 + kgB) ^ laneRow) << 4));
                ldsm4(b[j], addr);
            }
#pragma unroll
            for (int m = 0; m < 4; m++)
#pragma unroll
                for (int t = 0; t < 4; t++)
                    mma16816(acc[m][t], a[m],
                             b[t >> 1][(t & 1) << 1],
                             b[t >> 1][((t & 1) << 1) + 1]);
        }
        __syncthreads();
    }

    // epilogue: write sq directly (fragment c-layout)
    const int crow = c0 + mA + (lane >> 2);
    const int ncol = n0 + nB + ((lane & 3) << 1);
#pragma unroll
    for (int m = 0; m < 4; m++) {
#pragma unroll
        for (int t = 0; t < 4; t++) {
            float2 v0 = make_float2(acc[m][t][0], acc[m][t][1]);
            float2 v1 = make_float2(acc[m][t][2], acc[m][t][3]);
            *(float2*)(g_sq + (size_t)(crow + 16 * m)     * NN + ncol + 8 * t) = v0;
            *(float2*)(g_sq + (size_t)(crow + 16 * m + 8) * NN + ncol + 8 * t) = v1;
        }
    }
}

// ---------------------------------------------------------------------------
// Kernel 5: softmax over c, logits = gamma*(sq[c,n] + k_c); writes Pi rows.
// ---------------------------------------------------------------------------
__global__ __launch_bounds__(256) void softmax_kernel(const float* __restrict__ gamma_p,
                                                      float* __restrict__ out) {
    __shared__ float tile[32 * 257];
    __shared__ float sk[KK];
    const float g = *gamma_p;
    const int n0 = blockIdx.x * 32;
    const int tid = threadIdx.x;

    for (int i = tid; i < KK; i += 256) sk[i] = g_kc[i];
    for (int i = tid; i < 32 * KK; i += 256) {
        int cc = i >> 5, nl = i & 31;
        tile[nl * 257 + cc] = g_sq[(size_t)cc * NN + n0 + nl];
    }
    __syncthreads();

    const int warp = tid >> 5, lane = tid & 31;
    for (int r = warp; r < 32; r += 8) {
        float v[8];
        float m = -CUDART_INF_F;
#pragma unroll
        for (int u = 0; u < 8; u++) {
            int c = lane + 32 * u;
            v[u] = g * (tile[r * 257 + c] + sk[c]);
            m = fmaxf(m, v[u]);
        }
#pragma unroll
        for (int o = 16; o > 0; o >>= 1)
            m = fmaxf(m, __shfl_xor_sync(0xffffffffu, m, o));
        float s = 0.f;
#pragma unroll
        for (int u = 0; u < 8; u++) {
            v[u] = __expf(v[u] - m);
            s += v[u];
        }
#pragma unroll
        for (int o = 16; o > 0; o >>= 1)
            s += __shfl_xor_sync(0xffffffffu, s, o);
        float inv = __frcp_rn(s);
#pragma unroll
        for (int u = 0; u < 8; u++)
            tile[r * 257 + lane + 32 * u] = v[u] * inv;
    }
    __syncthreads();

    for (int i = tid; i < 32 * KK; i += 256) {
        int c = i >> 5, j = i & 31;
        out[(size_t)(DD + c) * NN + n0 + j] = tile[j * 257 + c];
    }
}

// ---------------------------------------------------------------------------
extern "C" void kernel_launch(void* const* d_in, const int* in_sizes, int n_in,
                              void* d_out, int out_size) {
    const float* X     = (const float*)d_in[0];  // (D, N)
    const float* NA    = (const float*)d_in[1];  // (D, D, K)
    const float* Nmu   = (const float*)d_in[2];  // (D, K)
    const float* gamma = (const float*)d_in[3];  // scalar
    float* out = (float*)d_out;                  // (D+K, N)

    cudaFuncSetAttribute(gbuild_kernel, cudaFuncAttributeMaxDynamicSharedMemorySize,
                         128 * 132 * 4 + 1024);
    cudaFuncSetAttribute(mma_kernel, cudaFuncAttributeMaxDynamicSharedMemorySize,
                         NST * STAGE_BYTES);

    // rows 0..D-1 of out = X verbatim
    cudaMemcpyAsync(out, X, (size_t)DD * NN * sizeof(float),
                    cudaMemcpyDeviceToDevice, 0);

    transpose_kernel<<<dim3((DD * DD) / 32, KK / 32), dim3(32, 8)>>>(NA);
    lut_kernel<<<1, 256>>>();
    gbuild_kernel<<<KK, 256, 128 * 132 * 4 + 1024>>>(Nmu);
    fbuild_kernel<<<NN / 32, 256>>>(X);
    mma_kernel<<<dim3(2, 64), 256, NST * STAGE_BYTES>>>();
    softmax_kernel<<<NN / 32, 256>>>(gamma, out);
}

// round 7
// speedup vs baseline: 12.0068x; 1.0875x over previous
#include <cuda_runtime.h>
#include <cuda_fp16.h>
#include <cstdint>
#include <math_constants.h>

#define DD 128
#define NN 8192
#define KK 256
#define RQ 8256            // d<=e pair rows
#define RTOT 8384          // + 128 linear rows (131 * 64)
#define KC 64              // k-chunk (halves)
#define NCH (RTOT / KC)    // 131
#define NST 3              // pipeline stages
#define STAGE_BYTES 32768  // 16KB A + 16KB B per stage
#define RSPLIT 4           // fbuild r-splits
#define RSEG (RTOT / RSPLIT)   // 2096

// ------------- device scratch (no allocations allowed) ---------------------
__device__ __align__(16) float  g_At[KK * DD * DD];      // A_c row-major per c (16 MB)
__device__ __align__(16) __half g_C[(size_t)KK * RTOT];  // coeff matrix fp16 (4.3 MB)
__device__ __align__(16) __half g_F[(size_t)NN * RTOT];  // feature matrix fp16 (137 MB)
__device__ __align__(16) float  g_sq[(size_t)2 * KK * NN]; // sq partials, 2 k-slabs
__device__ float g_kc[KK];                               // per-c constant
__device__ __align__(16) unsigned short g_lut[RTOT];     // r -> (d<<8)|e

// ------------------------------- PTX helpers -------------------------------
__device__ __forceinline__ uint32_t smem_u32(const void* p) {
    uint32_t a;
    asm("{ .reg .u64 t; cvta.to.shared.u64 t, %1; cvt.u32.u64 %0, t; }"
        : "=r"(a) : "l"(p));
    return a;
}
__device__ __forceinline__ void cp16h(uint32_t dst, const __half* src) {
    asm volatile("cp.async.cg.shared.global [%0], [%1], 16;"
                 :: "r"(dst), "l"((unsigned long long)__cvta_generic_to_global(src)));
}
#define CP_COMMIT() asm volatile("cp.async.commit_group;" ::: "memory")
#define CP_WAIT2()  asm volatile("cp.async.wait_group 2;" ::: "memory")

__device__ __forceinline__ void ldsm4(uint32_t* r, uint32_t addr) {
    asm volatile("ldmatrix.sync.aligned.m8n8.x4.shared.b16 {%0,%1,%2,%3}, [%4];"
                 : "=r"(r[0]), "=r"(r[1]), "=r"(r[2]), "=r"(r[3]) : "r"(addr));
}
__device__ __forceinline__ void mma16816(float* c, const uint32_t* a,
                                         uint32_t b0, uint32_t b1) {
    asm volatile(
        "mma.sync.aligned.m16n8k16.row.col.f32.f16.f16.f32 "
        "{%0,%1,%2,%3}, {%4,%5,%6,%7}, {%8,%9}, {%0,%1,%2,%3};"
        : "+f"(c[0]), "+f"(c[1]), "+f"(c[2]), "+f"(c[3])
        : "r"(a[0]), "r"(a[1]), "r"(a[2]), "r"(a[3]), "r"(b0), "r"(b1));
}

// ---------------------------------------------------------------------------
// Kernel 0: transpose N_A (16384 x 256) -> At (256 x 16384)
// ---------------------------------------------------------------------------
__global__ void transpose_kernel(const float* __restrict__ NA) {
    __shared__ float t[32][33];
    int r0 = blockIdx.x * 32;
    int c0 = blockIdx.y * 32;
    int tx = threadIdx.x, ty = threadIdx.y;
#pragma unroll
    for (int i = ty; i < 32; i += 8)
        t[i][tx] = NA[(r0 + i) * KK + c0 + tx];
    __syncthreads();
#pragma unroll
    for (int i = ty; i < 32; i += 8)
        g_At[(size_t)(c0 + i) * (DD * DD) + r0 + tx] = t[tx][i];
}

// ---------------------------------------------------------------------------
// Kernel 1: pair-index lookup table  r -> (d<<8)|e
// ---------------------------------------------------------------------------
__global__ void lut_kernel() {
    int t = threadIdx.x;
    if (t < 128) {
        int d = t;
        int base = d * DD - (d * (d - 1)) / 2;
        for (int e = d; e < DD; e++)
            g_lut[base + e - d] = (unsigned short)((d << 8) | e);
    } else {
        int e = t - 128;
        g_lut[RQ + e] = (unsigned short)((128 << 8) | e);
    }
}

// ---------------------------------------------------------------------------
// Kernel 2: per-c coefficients. G_c = A_c^T A_c, w_c = G mu, k_c = mu^T G mu.
// ---------------------------------------------------------------------------
__global__ __launch_bounds__(256, 2) void gbuild_kernel(const float* __restrict__ mu) {
    extern __shared__ float sm[];
    float* sA  = sm;                   // [128][132]
    float* smu = sm + 128 * 132;       // [128]
    float* ss  = smu + 128;            // [128]
    const int c = blockIdx.x, tid = threadIdx.x;

    const float* Ac = g_At + (size_t)c * (DD * DD);
    for (int i = tid * 4; i < DD * DD; i += 1024) {
        float4 v = *(const float4*)(Ac + i);
        int k = i >> 7, e = i & 127;
        *(float4*)(sA + k * 132 + e) = v;
    }
    if (tid < DD) smu[tid] = mu[tid * KK + c];
    __syncthreads();

    if (tid < DD) {                    // s[k] = A_c row k . mu
        float s = 0.f;
#pragma unroll 8
        for (int e = 0; e < DD; e++) s += sA[tid * 132 + e] * smu[e];
        ss[tid] = s;
    }
    __syncthreads();
    if (tid < DD) {                    // w[d] = sum_k A[k][d] s[k]
        float w = 0.f;
#pragma unroll 8
        for (int k = 0; k < DD; k++) w += sA[k * 132 + tid] * ss[k];
        g_C[(size_t)c * RTOT + RQ + tid] = __float2half(-2.f * w);
    }
    if (tid == 0) {                    // k_c = ||s||^2
        float kk = 0.f;
        for (int k = 0; k < DD; k++) kk += ss[k] * ss[k];
        g_kc[c] = kk;
    }

    // G = A^T A, 8x8 per thread
    const int tx = tid & 15, ty = tid >> 4;
    float acc[8][8] = {};
#pragma unroll 4
    for (int k = 0; k < DD; k++) {
        float a[8], b[8];
        *(float4*)(a)     = *(const float4*)(sA + k * 132 + ty * 8);
        *(float4*)(a + 4) = *(const float4*)(sA + k * 132 + ty * 8 + 4);
        *(float4*)(b)     = *(const float4*)(sA + k * 132 + tx * 8);
        *(float4*)(b + 4) = *(const float4*)(sA + k * 132 + tx * 8 + 4);
#pragma unroll
        for (int i = 0; i < 8; i++)
#pragma unroll
            for (int j = 0; j < 8; j++)
                acc[i][j] += a[i] * b[j];
    }
    __half* Crow = g_C + (size_t)c * RTOT;
#pragma unroll
    for (int i = 0; i < 8; i++) {
        int d = ty * 8 + i;
        int sd = d * DD - (d * (d - 1)) / 2;
#pragma unroll
        for (int j = 0; j < 8; j++) {
            int e = tx * 8 + j;
            if (e >= d)
                Crow[sd + e - d] = __float2half((e == d ? 1.f : 2.f) * acc[i][j]);
        }
    }
}

// ---------------------------------------------------------------------------
// Kernel 3: feature matrix F[n][r] = x_d[n]*x_e[n] (fp16). Grid (N/32, RSPLIT)
// so each CTA covers 32 n-cols x RSEG r-rows -> 1024 CTAs for occupancy.
// ---------------------------------------------------------------------------
__global__ __launch_bounds__(256) void fbuild_kernel(const float* __restrict__ X) {
    __shared__ __align__(16) float xs[129 * 33 + 3];
    __shared__ __align__(16) unsigned short slut[RSEG];
    const int tid = threadIdx.x;
    const int n0 = blockIdx.x * 32;
    const int rb = blockIdx.y * RSEG;

    for (int i = tid; i < DD * 32; i += 256) {
        int e = i >> 5, nl = i & 31;
        xs[e * 33 + nl] = X[e * NN + n0 + nl];
    }
    if (tid < 32) xs[128 * 33 + tid] = 1.0f;
    for (int i = tid; i < RSEG; i += 256) slut[i] = g_lut[rb + i];
    __syncthreads();

    for (int nl = 0; nl < 32; nl++) {
        __half* dst = g_F + (size_t)(n0 + nl) * RTOT + rb;
        for (int r4 = tid * 4; r4 < RSEG; r4 += 1024) {
            uint2 lw = *(const uint2*)(slut + r4);
            int d0 = (lw.x >> 8) & 0xFF,  e0 = lw.x & 0xFF;
            int d1 = (lw.x >> 24) & 0xFF, e1 = (lw.x >> 16) & 0xFF;
            int d2 = (lw.y >> 8) & 0xFF,  e2 = lw.y & 0xFF;
            int d3 = (lw.y >> 24) & 0xFF, e3 = (lw.y >> 16) & 0xFF;
            __half2 h0 = __floats2half2_rn(xs[d0 * 33 + nl] * xs[e0 * 33 + nl],
                                           xs[d1 * 33 + nl] * xs[e1 * 33 + nl]);
            __half2 h1 = __floats2half2_rn(xs[d2 * 33 + nl] * xs[e2 * 33 + nl],
                                           xs[d3 * 33 + nl] * xs[e3 * 33 + nl]);
            uint2 v;
            v.x = *reinterpret_cast<uint32_t*>(&h0);
            v.y = *reinterpret_cast<uint32_t*>(&h1);
            *(uint2*)(dst + r4) = v;
        }
    }
}

// ---------------------------------------------------------------------------
// Kernel 4: fp16 mma.sync GEMM  sq[c,n] = sum_r C[c,r] * F[n,r]
// 4 warps, warp tile 64x64, CTA 128x128, 3-stage cp.async, split-k 2,
// 2 CTAs/SM. Grid (2, 64, 2).
// ---------------------------------------------------------------------------
__global__ __launch_bounds__(128, 2) void mma_kernel() {
    extern __shared__ char dsm[];
    const uint32_t sbase = smem_u32(dsm);
    const int tid = threadIdx.x, lane = tid & 31, wid = tid >> 5;
    const int c0 = blockIdx.x * 128, n0 = blockIdx.y * 128;
    const int kv = blockIdx.z;
    const int cbase = kv ? 66 : 0;
    const int nch = kv ? 65 : 66;
    const int mwarp = wid & 1, nwarp = wid >> 1;

    // stage loader: 128 threads x 8 iters cover 128 rows x 8 segs for A and B
    auto load_stage = [&](int st, int ch) {
        uint32_t ab = sbase + st * STAGE_BYTES;
        uint32_t bb = ab + 16384;
        const __half* As = g_C + (size_t)c0 * RTOT + ch * KC;
        const __half* Bs = g_F + (size_t)n0 * RTOT + ch * KC;
#pragma unroll
        for (int j = 0; j < 8; j++) {
            int seg = tid + j * 128;          // 0..1023
            int row = seg >> 3, s = seg & 7;
            uint32_t off = (uint32_t)(row * 128 + ((s ^ (row & 7)) << 4));
            cp16h(ab + off, As + (size_t)row * RTOT + s * 8);
            cp16h(bb + off, Bs + (size_t)row * RTOT + s * 8);
        }
        CP_COMMIT();
    };

    load_stage(0, cbase);
    load_stage(1, cbase + 1);

    float acc[4][8][4] = {};

    const int laneRow = lane & 7;
    const int grp = lane >> 3;               // 0..3
    const int rowOffA = (grp & 1) << 3;      // A: +8 rows for odd groups
    const int kgA = grp >> 1;                // A: +8 k for groups 2,3
    const int rowOffB = (lane >> 4) << 3;    // B: +8 n-rows for t16..31
    const int kgB = (lane >> 3) & 1;         // B: +8 k for groups 1,3
    const int mA = mwarp * 64, nB = nwarp * 64;

    for (int i = 0; i < nch; i++) {
        if (i + 2 < nch) load_stage((i + 2) % 3, cbase + i + 2);
        else CP_COMMIT();
        CP_WAIT2();
        __syncthreads();

        uint32_t ab = sbase + (i % 3) * STAGE_BYTES;
        uint32_t bb = ab + 16384;
#pragma unroll
        for (int ks = 0; ks < 4; ks++) {     // 4 x k16 steps within chunk
            uint32_t a[4][4], b[4][4];
#pragma unroll
            for (int m = 0; m < 4; m++) {
                int row = mA + 16 * m + laneRow + rowOffA;
                uint32_t addr = ab + (uint32_t)(row * 128 +
                                (((ks * 2 + kgA) ^ laneRow) << 4));
                ldsm4(a[m], addr);
            }
#pragma unroll
            for (int j = 0; j < 4; j++) {
                int row = nB + 16 * j + laneRow + rowOffB;
                uint32_t addr = bb + (uint32_t)(row * 128 +
                                (((ks * 2 + kgB) ^ laneRow) << 4));
                ldsm4(b[j], addr);
            }
#pragma unroll
            for (int m = 0; m < 4; m++)
#pragma unroll
                for (int t = 0; t < 8; t++)
                    mma16816(acc[m][t], a[m],
                             b[t >> 1][(t & 1) << 1],
                             b[t >> 1][((t & 1) << 1) + 1]);
        }
        __syncthreads();
    }

    // epilogue: write partial sq into slab kv
    float* slab = g_sq + (size_t)kv * KK * NN;
    const int crow = c0 + mA + (lane >> 2);
    const int ncol = n0 + nB + ((lane & 3) << 1);
#pragma unroll
    for (int m = 0; m < 4; m++) {
#pragma unroll
        for (int t = 0; t < 8; t++) {
            float2 v0 = make_float2(acc[m][t][0], acc[m][t][1]);
            float2 v1 = make_float2(acc[m][t][2], acc[m][t][3]);
            *(float2*)(slab + (size_t)(crow + 16 * m)     * NN + ncol + 8 * t) = v0;
            *(float2*)(slab + (size_t)(crow + 16 * m + 8) * NN + ncol + 8 * t) = v1;
        }
    }
}

// ---------------------------------------------------------------------------
// Kernel 5: softmax over c; logits = gamma*(sq0 + sq1 + k_c); writes Pi rows.
// ---------------------------------------------------------------------------
__global__ __launch_bounds__(256) void softmax_kernel(const float* __restrict__ gamma_p,
                                                      float* __restrict__ out) {
    __shared__ float tile[32 * 257];
    __shared__ float sk[KK];
    const float g = *gamma_p;
    const int n0 = blockIdx.x * 32;
    const int tid = threadIdx.x;

    for (int i = tid; i < KK; i += 256) sk[i] = g_kc[i];
    for (int i = tid; i < 32 * KK; i += 256) {
        int cc = i >> 5, nl = i & 31;
        tile[nl * 257 + cc] = g_sq[(size_t)cc * NN + n0 + nl]
                            + g_sq[(size_t)(KK + cc) * NN + n0 + nl];
    }
    __syncthreads();

    const int warp = tid >> 5, lane = tid & 31;
    for (int r = warp; r < 32; r += 8) {
        float v[8];
        float m = -CUDART_INF_F;
#pragma unroll
        for (int u = 0; u < 8; u++) {
            int c = lane + 32 * u;
            v[u] = g * (tile[r * 257 + c] + sk[c]);
            m = fmaxf(m, v[u]);
        }
#pragma unroll
        for (int o = 16; o > 0; o >>= 1)
            m = fmaxf(m, __shfl_xor_sync(0xffffffffu, m, o));
        float s = 0.f;
#pragma unroll
        for (int u = 0; u < 8; u++) {
            v[u] = __expf(v[u] - m);
            s += v[u];
        }
#pragma unroll
        for (int o = 16; o > 0; o >>= 1)
            s += __shfl_xor_sync(0xffffffffu, s, o);
        float inv = __frcp_rn(s);
#pragma unroll
        for (int u = 0; u < 8; u++)
            tile[r * 257 + lane + 32 * u] = v[u] * inv;
    }
    __syncthreads();

    for (int i = tid; i < 32 * KK; i += 256) {
        int c = i >> 5, j = i & 31;
        out[(size_t)(DD + c) * NN + n0 + j] = tile[j * 257 + c];
    }
}

// ---------------------------------------------------------------------------
extern "C" void kernel_launch(void* const* d_in, const int* in_sizes, int n_in,
                              void* d_out, int out_size) {
    const float* X     = (const float*)d_in[0];  // (D, N)
    const float* NA    = (const float*)d_in[1];  // (D, D, K)
    const float* Nmu   = (const float*)d_in[2];  // (D, K)
    const float* gamma = (const float*)d_in[3];  // scalar
    float* out = (float*)d_out;                  // (D+K, N)

    cudaFuncSetAttribute(gbuild_kernel, cudaFuncAttributeMaxDynamicSharedMemorySize,
                         128 * 132 * 4 + 1024);
    cudaFuncSetAttribute(mma_kernel, cudaFuncAttributeMaxDynamicSharedMemorySize,
                         NST * STAGE_BYTES);

    // rows 0..D-1 of out = X verbatim
    cudaMemcpyAsync(out, X, (size_t)DD * NN * sizeof(float),
                    cudaMemcpyDeviceToDevice, 0);

    transpose_kernel<<<dim3((DD * DD) / 32, KK / 32), dim3(32, 8)>>>(NA);
    lut_kernel<<<1, 256>>>();
    gbuild_kernel<<<KK, 256, 128 * 132 * 4 + 1024>>>(Nmu);
    fbuild_kernel<<<dim3(NN / 32, RSPLIT), 256>>>(X);
    mma_kernel<<<dim3(2, 64, 2), 128, NST * STAGE_BYTES>>>();
    softmax_kernel<<<NN / 32, 256>>>(gamma, out);
}

// round 10
// speedup vs baseline: 13.3878x; 1.1150x over previous
#include <cuda_runtime.h>
#include <cuda_fp16.h>
#include <cstdint>
#include <math_constants.h>

#define DD 128
#define NN 8192
#define KK 256
#define RQPAD 8704         // front-aligned pair rows: row d spans e in [8*(d/8), 128)
#define RTOT 8832          // + 128 linear rows  (= 138 * 64)
#define NSEG 1104          // RTOT / 8
#define SEGSPLIT 4
#define SEGPB (NSEG / SEGSPLIT)   // 276
#define XROW 136           // halves per xs2 row (128 + 1.0 marker + zeros)
#define KC 64              // k-chunk (halves)
#define NCH (RTOT / KC)    // 138
#define NST 3              // pipeline stages
#define STAGE_BYTES 32768  // 16KB A + 16KB B per stage

// ------------- device scratch (no allocations allowed) ---------------------
__device__ __align__(16) float  g_At[KK * DD * DD];      // A_c row-major per c (16 MB)
__device__ __align__(16) __half g_C[(size_t)KK * RTOT];  // coeff matrix fp16
__device__ __align__(16) __half g_F[(size_t)NN * RTOT];  // feature matrix fp16 (145 MB)
__device__ __align__(16) float  g_sq[(size_t)2 * KK * NN]; // sq partials, 2 k-slabs
__device__ float g_kc[KK];                               // per-c constant
__device__ __align__(16) unsigned short g_lut[NSEG];     // seg -> (d<<8)|e0 (e0 8-aligned)
__device__ int g_rowbase[129];                           // padded prefix sums

// ------------------------------- PTX helpers -------------------------------
__device__ __forceinline__ uint32_t smem_u32(const void* p) {
    uint32_t a;
    asm("{ .reg .u64 t; cvta.to.shared.u64 t, %1; cvt.u32.u64 %0, t; }"
        : "=r"(a) : "l"(p));
    return a;
}
__device__ __forceinline__ void cp16h(uint32_t dst, const __half* src) {
    asm volatile("cp.async.cg.shared.global [%0], [%1], 16;"
                 :: "r"(dst), "l"((unsigned long long)__cvta_generic_to_global(src)));
}
#define CP_COMMIT() asm volatile("cp.async.commit_group;" ::: "memory")
#define CP_WAIT2()  asm volatile("cp.async.wait_group 2;" ::: "memory")

__device__ __forceinline__ void ldsm4(uint32_t* r, uint32_t addr) {
    asm volatile("ldmatrix.sync.aligned.m8n8.x4.shared.b16 {%0,%1,%2,%3}, [%4];"
                 : "=r"(r[0]), "=r"(r[1]), "=r"(r[2]), "=r"(r[3]) : "r"(addr));
}
__device__ __forceinline__ void mma16816(float* c, const uint32_t* a,
                                         uint32_t b0, uint32_t b1) {
    asm volatile(
        "mma.sync.aligned.m16n8k16.row.col.f32.f16.f16.f32 "
        "{%0,%1,%2,%3}, {%4,%5,%6,%7}, {%8,%9}, {%0,%1,%2,%3};"
        : "+f"(c[0]), "+f"(c[1]), "+f"(c[2]), "+f"(c[3])
        : "r"(a[0]), "r"(a[1]), "r"(a[2]), "r"(a[3]), "r"(b0), "r"(b1));
}

// ---------------------------------------------------------------------------
// Kernel 0: transpose N_A (16384 x 256) -> At (256 x 16384)
// ---------------------------------------------------------------------------
__global__ void transpose_kernel(const float* __restrict__ NA) {
    __shared__ float t[32][33];
    int r0 = blockIdx.x * 32;
    int c0 = blockIdx.y * 32;
    int tx = threadIdx.x, ty = threadIdx.y;
#pragma unroll
    for (int i = ty; i < 32; i += 8)
        t[i][tx] = NA[(r0 + i) * KK + c0 + tx];
    __syncthreads();
#pragma unroll
    for (int i = ty; i < 32; i += 8)
        g_At[(size_t)(c0 + i) * (DD * DD) + r0 + tx] = t[tx][i];
}

// ---------------------------------------------------------------------------
// Kernel 1: rowbase prefix sums + segment LUT. Row d: e0 starts at 8*(d/8),
// ns = 16 - d/8 segments, all 8-aligned. Linear rows after RQPAD.
// ---------------------------------------------------------------------------
__global__ void lut_kernel() {
    __shared__ int srb[129];
    int t = threadIdx.x;
    if (t == 0) {
        int acc = 0;
        for (int d = 0; d < 128; d++) {
            srb[d] = acc;
            acc += 128 - 8 * (d >> 3);
        }
        srb[128] = acc;                     // 8704
    }
    __syncthreads();
    if (t < 129) g_rowbase[t] = srb[t];
    if (t < 128) {
        int d = t, fd = d >> 3;
        int sb = srb[d] / 8, ns = 16 - fd;
        for (int s = 0; s < ns; s++)
            g_lut[sb + s] = (unsigned short)((d << 8) | (8 * (fd + s)));
    } else if (t < 144) {
        int s = t - 128;                    // 16 linear segments (d marker 128)
        g_lut[RQPAD / 8 + s] = (unsigned short)((128 << 8) | (s * 8));
    }
}

// ---------------------------------------------------------------------------
// Kernel 2: per-c coefficients. G_c = A_c^T A_c (upper tiles only), w_c, k_c.
// C row d at srb[d], index e - 8*(d/8); front padding (e<d) written as 0
// inside the diagonal tile.
// ---------------------------------------------------------------------------
__global__ __launch_bounds__(256, 2) void gbuild_kernel(const float* __restrict__ mu) {
    extern __shared__ float sm[];
    float* sA  = sm;                   // [128][132]
    float* smu = sm + 128 * 132;       // [128]
    float* ss  = smu + 128;            // [128]
    int*   srb = (int*)(ss + 128);     // [129]
    const int c = blockIdx.x, tid = threadIdx.x;

    const float* Ac = g_At + (size_t)c * (DD * DD);
    for (int i = tid * 4; i < DD * DD; i += 1024) {
        float4 v = *(const float4*)(Ac + i);
        int k = i >> 7, e = i & 127;
        *(float4*)(sA + k * 132 + e) = v;
    }
    if (tid < DD) smu[tid] = mu[tid * KK + c];
    if (tid < 129) srb[tid] = g_rowbase[tid];
    __syncthreads();

    if (tid < DD) {                    // s[k] = A_c row k . mu
        float s = 0.f;
#pragma unroll 8
        for (int e = 0; e < DD; e++) s += sA[tid * 132 + e] * smu[e];
        ss[tid] = s;
    }
    __syncthreads();
    if (tid < DD) {                    // w[d] = sum_k A[k][d] s[k]
        float w = 0.f;
#pragma unroll 8
        for (int k = 0; k < DD; k++) w += sA[k * 132 + tid] * ss[k];
        g_C[(size_t)c * RTOT + RQPAD + tid] = __float2half(-2.f * w);
    }
    if (tid == 0) {                    // k_c = ||s||^2
        float kk = 0.f;
        for (int k = 0; k < DD; k++) kk += ss[k] * ss[k];
        g_kc[c] = kk;
    }

    // G = A^T A; only tiles with tx >= ty do work (upper triangle + diagonal)
    const int tx = tid & 15, ty = tid >> 4;
    float acc[8][8] = {};
    if (tx >= ty) {
#pragma unroll 4
        for (int k = 0; k < DD; k++) {
            float a[8], b[8];
            *(float4*)(a)     = *(const float4*)(sA + k * 132 + ty * 8);
            *(float4*)(a + 4) = *(const float4*)(sA + k * 132 + ty * 8 + 4);
            *(float4*)(b)     = *(const float4*)(sA + k * 132 + tx * 8);
            *(float4*)(b + 4) = *(const float4*)(sA + k * 132 + tx * 8 + 4);
#pragma unroll
            for (int i = 0; i < 8; i++)
#pragma unroll
                for (int j = 0; j < 8; j++)
                    acc[i][j] += a[i] * b[j];
        }
        __half* Crow = g_C + (size_t)c * RTOT;
#pragma unroll
        for (int i = 0; i < 8; i++) {
            int d = ty * 8 + i;
            int base = srb[d] - 8 * ty;    // index = srb[d] + e - 8*(d>>3); d>>3 == ty
#pragma unroll
            for (int j = 0; j < 8; j++) {
                int e = tx * 8 + j;
                float v = (e < d) ? 0.f : (e == d ? 1.f : 2.f) * acc[i][j];
                Crow[base + e] = __float2half(v);
            }
        }
    }
}

// ---------------------------------------------------------------------------
// Kernel 3: feature matrix F, aligned-segment layout.
// Segment (d, e0): F[...] = x_d * x_{e0..e0+7}, e0 always 8-aligned.
// Grid (N/32, SEGSPLIT). Per segment: 1 LDS + 1 LDS.128 + 4 HMUL2 + STG.128.
// ---------------------------------------------------------------------------
__global__ __launch_bounds__(256) void fbuild_kernel(const float* __restrict__ X) {
    __shared__ __align__(16) __half xs2[32 * XROW];
    __shared__ __align__(4) unsigned short slut[SEGPB];
    const int tid = threadIdx.x, lane = tid & 31, warp = tid >> 5;
    const int n0 = blockIdx.x * 32;
    const int sb = blockIdx.y * SEGPB;

    // transpose-load X tile: lane holds 8 consecutive-e halves for its nl
#pragma unroll
    for (int it = 0; it < 2; it++) {
        int e0 = (warp + 8 * it) * 8;
        float v[8];
#pragma unroll
        for (int j = 0; j < 8; j++) v[j] = X[(size_t)(e0 + j) * NN + n0 + lane];
        __half2 h[4];
#pragma unroll
        for (int k = 0; k < 4; k++) h[k] = __floats2half2_rn(v[2 * k], v[2 * k + 1]);
        *(uint4*)(xs2 + lane * XROW + e0) = *(uint4*)h;
    }
    if (tid < 32 * 8) {        // xs2[nl][128] = 1.0 (linear rows), 129..135 = 0
        int nl = tid >> 3, j = tid & 7;
        xs2[nl * XROW + 128 + j] = (j == 0) ? __float2half(1.0f) : __half(0);
    }
    for (int i = tid; i < SEGPB; i += 256) slut[i] = g_lut[sb + i];
    __syncthreads();

    for (int nl = 0; nl < 32; nl++) {
        const __half* xrow = xs2 + nl * XROW;
        __half* dst = g_F + (size_t)(n0 + nl) * RTOT + sb * 8;
        for (int s = tid; s < SEGPB; s += 256) {
            unsigned short lw = slut[s];
            int d = lw >> 8, e0 = lw & 255;
            __half2 xd2 = __half2half2(xrow[d]);
            __half2 xe[4];
            *(uint4*)xe = *(const uint4*)(xrow + e0);   // e0 8-aligned -> 16B ok
            __half2 o[4];
#pragma unroll
            for (int k = 0; k < 4; k++) o[k] = __hmul2(xe[k], xd2);
            *(uint4*)(dst + s * 8) = *(uint4*)o;
        }
    }
}

// ---------------------------------------------------------------------------
// Kernel 4: fp16 mma.sync GEMM  sq[c,n] = sum_r C[c,r] * F[n,r]
// 4 warps, warp tile 64x64, CTA 128x128, 3-stage cp.async, split-k 2.
// ---------------------------------------------------------------------------
__global__ __launch_bounds__(128, 2) void mma_kernel() {
    extern __shared__ char dsm[];
    const uint32_t sbase = smem_u32(dsm);
    const int tid = threadIdx.x, lane = tid & 31, wid = tid >> 5;
    const int c0 = blockIdx.x * 128, n0 = blockIdx.y * 128;
    const int kv = blockIdx.z;
    const int cbase = kv * (NCH / 2);
    const int nch = NCH / 2;
    const int mwarp = wid & 1, nwarp = wid >> 1;

    auto load_stage = [&](int st, int ch) {
        uint32_t ab = sbase + st * STAGE_BYTES;
        uint32_t bb = ab + 16384;
        const __half* As = g_C + (size_t)c0 * RTOT + ch * KC;
        const __half* Bs = g_F + (size_t)n0 * RTOT + ch * KC;
#pragma unroll
        for (int j = 0; j < 8; j++) {
            int seg = tid + j * 128;          // 0..1023
            int row = seg >> 3, s = seg & 7;
            uint32_t off = (uint32_t)(row * 128 + ((s ^ (row & 7)) << 4));
            cp16h(ab + off, As + (size_t)row * RTOT + s * 8);
            cp16h(bb + off, Bs + (size_t)row * RTOT + s * 8);
        }
        CP_COMMIT();
    };

    load_stage(0, cbase);
    load_stage(1, cbase + 1);

    float acc[4][8][4] = {};

    const int laneRow = lane & 7;
    const int grp = lane >> 3;               // 0..3
    const int rowOffA = (grp & 1) << 3;      // A: +8 rows for odd groups
    const int kgA = grp >> 1;                // A: +8 k for groups 2,3
    const int rowOffB = (lane >> 4) << 3;    // B: +8 n-rows for t16..31
    const int kgB = (lane >> 3) & 1;         // B: +8 k for groups 1,3
    const int mA = mwarp * 64, nB = nwarp * 64;

    for (int i = 0; i < nch; i++) {
        if (i + 2 < nch) load_stage((i + 2) % 3, cbase + i + 2);
        else CP_COMMIT();
        CP_WAIT2();
        __syncthreads();

        uint32_t ab = sbase + (i % 3) * STAGE_BYTES;
        uint32_t bb = ab + 16384;
#pragma unroll
        for (int ks = 0; ks < 4; ks++) {
            uint32_t a[4][4], b[4][4];
#pragma unroll
            for (int m = 0; m < 4; m++) {
                int row = mA + 16 * m + laneRow + rowOffA;
                uint32_t addr = ab + (uint32_t)(row * 128 +
                                (((ks * 2 + kgA) ^ laneRow) << 4));
                ldsm4(a[m], addr);
            }
#pragma unroll
            for (int j = 0; j < 4; j++) {
                int row = nB + 16 * j + laneRow + rowOffB;
                uint32_t addr = bb + (uint32_t)(row * 128 +
                                (((ks * 2 + kgB) ^ laneRow) << 4));
                ldsm4(b[j], addr);
            }
#pragma unroll
            for (int m = 0; m < 4; m++)
#pragma unroll
                for (int t = 0; t < 8; t++)
                    mma16816(acc[m][t], a[m],
                             b[t >> 1][(t & 1) << 1],
                             b[t >> 1][((t & 1) << 1) + 1]);
        }
        __syncthreads();
    }

    float* slab = g_sq + (size_t)kv * KK * NN;
    const int crow = c0 + mA + (lane >> 2);
    const int ncol = n0 + nB + ((lane & 3) << 1);
#pragma unroll
    for (int m = 0; m < 4; m++) {
#pragma unroll
        for (int t = 0; t < 8; t++) {
            float2 v0 = make_float2(acc[m][t][0], acc[m][t][1]);
            float2 v1 = make_float2(acc[m][t][2], acc[m][t][3]);
            *(float2*)(slab + (size_t)(crow + 16 * m)     * NN + ncol + 8 * t) = v0;
            *(float2*)(slab + (size_t)(crow + 16 * m + 8) * NN + ncol + 8 * t) = v1;
        }
    }
}

// ---------------------------------------------------------------------------
// Kernel 5: softmax over c; logits = gamma*(sq0 + sq1 + k_c); writes Pi rows.
// ---------------------------------------------------------------------------
__global__ __launch_bounds__(256) void softmax_kernel(const float* __restrict__ gamma_p,
                                                      float* __restrict__ out) {
    __shared__ float tile[32 * 257];
    __shared__ float sk[KK];
    const float g = *gamma_p;
    const int n0 = blockIdx.x * 32;
    const int tid = threadIdx.x;

    for (int i = tid; i < KK; i += 256) sk[i] = g_kc[i];
    for (int i = tid; i < 32 * KK; i += 256) {
        int cc = i >> 5, nl = i & 31;
        tile[nl * 257 + cc] = g_sq[(size_t)cc * NN + n0 + nl]
                            + g_sq[(size_t)(KK + cc) * NN + n0 + nl];
    }
    __syncthreads();

    const int warp = tid >> 5, lane = tid & 31;
    for (int r = warp; r < 32; r += 8) {
        float v[8];
        float m = -CUDART_INF_F;
#pragma unroll
        for (int u = 0; u < 8; u++) {
            int c = lane + 32 * u;
            v[u] = g * (tile[r * 257 + c] + sk[c]);
            m = fmaxf(m, v[u]);
        }
#pragma unroll
        for (int o = 16; o > 0; o >>= 1)
            m = fmaxf(m, __shfl_xor_sync(0xffffffffu, m, o));
        float s = 0.f;
#pragma unroll
        for (int u = 0; u < 8; u++) {
            v[u] = __expf(v[u] - m);
            s += v[u];
        }
#pragma unroll
        for (int o = 16; o > 0; o >>= 1)
            s += __shfl_xor_sync(0xffffffffu, s, o);
        float inv = __frcp_rn(s);
#pragma unroll
        for (int u = 0; u < 8; u++)
            tile[r * 257 + lane + 32 * u] = v[u] * inv;
    }
    __syncthreads();

    for (int i = tid; i < 32 * KK; i += 256) {
        int c = i >> 5, j = i & 31;
        out[(size_t)(DD + c) * NN + n0 + j] = tile[j * 257 + c];
    }
}

// ---------------------------------------------------------------------------
extern "C" void kernel_launch(void* const* d_in, const int* in_sizes, int n_in,
                              void* d_out, int out_size) {
    const float* X     = (const float*)d_in[0];  // (D, N)
    const float* NA    = (const float*)d_in[1];  // (D, D, K)
    const float* Nmu   = (const float*)d_in[2];  // (D, K)
    const float* gamma = (const float*)d_in[3];  // scalar
    float* out = (float*)d_out;                  // (D+K, N)

    cudaFuncSetAttribute(gbuild_kernel, cudaFuncAttributeMaxDynamicSharedMemorySize,
                         (128 * 132 + 128 + 128 + 132) * 4 + 256);
    cudaFuncSetAttribute(mma_kernel, cudaFuncAttributeMaxDynamicSharedMemorySize,
                         NST * STAGE_BYTES);

    // rows 0..D-1 of out = X verbatim
    cudaMemcpyAsync(out, X, (size_t)DD * NN * sizeof(float),
                    cudaMemcpyDeviceToDevice, 0);

    transpose_kernel<<<dim3((DD * DD) / 32, KK / 32), dim3(32, 8)>>>(NA);
    lut_kernel<<<1, 256>>>();
    gbuild_kernel<<<KK, 256, (128 * 132 + 128 + 128 + 132) * 4 + 256>>>(Nmu);
    fbuild_kernel<<<dim3(NN / 32, SEGSPLIT), 256>>>(X);
    mma_kernel<<<dim3(2, 64, 2), 128, NST * STAGE_BYTES>>>();
    softmax_kernel<<<NN / 32, 256>>>(gamma, out);
}